// round 10
// baseline (speedup 1.0000x reference)
#include <cuda_runtime.h>
#include <float.h>

// features [4,256,50,50] f32, rois [128,5] f32 (b,x1,y1,x2,y2),
// out [128,256,7,7] f32. Caffe geometry with reciprocal-multiply bin size
// (bin = roi * fl32(1/7)) — verified bit-exact vs gold in round 9.
//
// ROUND 10 OPT: one thread = one bin x 8 channels (c_lo, c_lo+32, ...).
// Amortizes the ~40-instr ROI/edge prologue 8x and gives MLP=8 in the
// window loop. Warp lanes = consecutive bins of one (n, c_lo):
// loads stay inside one 50x50 plane, stores coalesced per k-slice.

#define NTHREADS_TOTAL (128 * 32 * 49)   // 200,704
#define PLANE 2500                        // 50*50
#define KSTRIDE (32 * PLANE)              // 80,000 floats between k-planes

__global__ void roi_pool_opt(const float* __restrict__ feat,
                             const float* __restrict__ rois,
                             float* __restrict__ out)
{
    const int tid = blockIdx.x * blockDim.x + threadIdx.x;
    if (tid >= NTHREADS_TOTAL) return;

    const int bin  = tid % 49;            // fastest -> coalesced stores
    const int c_lo = (tid / 49) % 32;
    const int n    = tid / (49 * 32);
    const int pw   = bin % 7;
    const int ph   = bin / 7;

    // ---- ROI decode (bit-exact round-9 semantics) ----
    const float* r = rois + n * 5;
    const int   b  = (int)r[0];
    const float x1 = rintf(r[1] * 0.0625f);
    const float y1 = rintf(r[2] * 0.0625f);
    const float x2 = rintf(r[3] * 0.0625f);
    const float y2 = rintf(r[4] * 0.0625f);

    const float roi_w = fmaxf(x2 - x1 + 1.0f, 1.0f);
    const float roi_h = fmaxf(y2 - y1 + 1.0f, 1.0f);

    const float C7 = 1.0f / 7.0f;                 // fl32(1/7), compile-time
    const float bw = __fmul_rn(roi_w, C7);        // reciprocal-multiply div
    const float bh = __fmul_rn(roi_h, C7);

    const float wstart = fminf(fmaxf(floorf(__fmul_rn((float)pw, bw))        + x1, 0.0f), 50.0f);
    const float wend   = fminf(fmaxf(ceilf (__fmul_rn((float)pw + 1.0f, bw)) + x1, 0.0f), 50.0f);
    const float hstart = fminf(fmaxf(floorf(__fmul_rn((float)ph, bh))        + y1, 0.0f), 50.0f);
    const float hend   = fminf(fmaxf(ceilf (__fmul_rn((float)ph + 1.0f, bh)) + y1, 0.0f), 50.0f);

    const int w0 = (int)wstart, w1 = (int)wend;
    const int h0 = (int)hstart, h1 = (int)hend;

    // ---- 8-channel pooling loop ----
    const float* __restrict__ p0 = feat + ((size_t)b * 256 + c_lo) * PLANE;

    float m[8];
#pragma unroll
    for (int k = 0; k < 8; ++k) m[k] = -FLT_MAX;

    for (int h = h0; h < h1; ++h) {
        const int rowoff = h * 50;
        for (int w = w0; w < w1; ++w) {
            const int off = rowoff + w;        // shared address math
#pragma unroll
            for (int k = 0; k < 8; ++k)
                m[k] = fmaxf(m[k], __ldg(p0 + off + k * KSTRIDE));
        }
    }

    const bool nonempty = (w1 > w0) && (h1 > h0);
    const int obase = (n * 256 + c_lo) * 49 + bin;
#pragma unroll
    for (int k = 0; k < 8; ++k)
        out[obase + k * (32 * 49)] = nonempty ? m[k] : 0.0f;
}

extern "C" void kernel_launch(void* const* d_in, const int* in_sizes, int n_in,
                              void* d_out, int out_size)
{
    const float* feat = nullptr;
    const float* rois = nullptr;
    for (int i = 0; i < n_in; ++i) {
        long s = in_sizes[i];
        if (s == 2560000L || s == 10240000L) feat = (const float*)d_in[i];
        else if (s == 640L || s == 2560L)    rois = (const float*)d_in[i];
    }
    if (!feat) feat = (const float*)d_in[0];
    if (!rois) rois = (const float*)d_in[n_in > 1 ? 1 : 0];

    const int threads = 256;
    const int blocks = (NTHREADS_TOTAL + threads - 1) / threads;  // 784
    roi_pool_opt<<<blocks, threads>>>(feat, rois, (float*)d_out);
}

// round 11
// speedup vs baseline: 1.2805x; 1.2805x over previous
#include <cuda_runtime.h>
#include <float.h>

// features [4,256,50,50] f32, rois [128,5] f32 (b,x1,y1,x2,y2),
// out [128,256,7,7] f32. Caffe geometry + reciprocal-multiply bin size
// (bin = roi * fl32(1/7)) — bit-exact vs gold (round 9).
//
// ROUND 11: two-phase. Phase 1 (tiny) computes per-(roi,bin) window edges
// once -> packed table in __device__ scratch. Phase 2 uses round-9's proven
// 1.6M-thread shape (issue=71.6%) with the ~40-instr prologue replaced by
// one cached 4-byte table load.

#define NBINS  49
#define NROI   128
#define OUT_ELEMS 1605632          // 128*256*49
#define PLANE  2500

// Packed edges: w0 | w1<<8 | h0<<16 | h1<<24. Batch idx table separate.
__device__ unsigned int g_edges[NROI * NBINS];
__device__ int          g_batch[NROI];

__global__ void edges_kernel(const float* __restrict__ rois)
{
    const int idx = blockIdx.x * blockDim.x + threadIdx.x;
    if (idx >= NROI * NBINS) return;

    const int bin = idx % NBINS;
    const int n   = idx / NBINS;
    const int pw  = bin % 7;
    const int ph  = bin / 7;

    const float* r = rois + n * 5;
    const float x1 = rintf(r[1] * 0.0625f);   // exact *2^-4, half-even
    const float y1 = rintf(r[2] * 0.0625f);
    const float x2 = rintf(r[3] * 0.0625f);
    const float y2 = rintf(r[4] * 0.0625f);

    const float roi_w = fmaxf(x2 - x1 + 1.0f, 1.0f);
    const float roi_h = fmaxf(y2 - y1 + 1.0f, 1.0f);

    const float C7 = 1.0f / 7.0f;             // fl32(1/7)
    const float bw = __fmul_rn(roi_w, C7);    // reciprocal-multiply div
    const float bh = __fmul_rn(roi_h, C7);

    const float wstart = fminf(fmaxf(floorf(__fmul_rn((float)pw, bw))        + x1, 0.0f), 50.0f);
    const float wend   = fminf(fmaxf(ceilf (__fmul_rn((float)pw + 1.0f, bw)) + x1, 0.0f), 50.0f);
    const float hstart = fminf(fmaxf(floorf(__fmul_rn((float)ph, bh))        + y1, 0.0f), 50.0f);
    const float hend   = fminf(fmaxf(ceilf (__fmul_rn((float)ph + 1.0f, bh)) + y1, 0.0f), 50.0f);

    const unsigned int w0 = (unsigned int)(int)wstart;
    const unsigned int w1 = (unsigned int)(int)wend;
    const unsigned int h0 = (unsigned int)(int)hstart;
    const unsigned int h1 = (unsigned int)(int)hend;

    g_edges[idx] = w0 | (w1 << 8) | (h0 << 16) | (h1 << 24);
    if (bin == 0) g_batch[n] = (int)r[0];
}

__global__ void pool_kernel(const float* __restrict__ feat,
                            float* __restrict__ out)
{
    const int idx = blockIdx.x * blockDim.x + threadIdx.x;
    if (idx >= OUT_ELEMS) return;

    // out [n, c, ph, pw]; bin fastest -> coalesced stores
    const int bin = idx % NBINS;
    const int c   = (idx / NBINS) & 255;
    const int n   = idx / (NBINS * 256);

    const unsigned int e = g_edges[n * NBINS + bin];  // L1-hot (49 per roi)
    const int w0 = (int)(e & 0xFF);
    const int w1 = (int)((e >> 8) & 0xFF);
    const int h0 = (int)((e >> 16) & 0xFF);
    const int h1 = (int)(e >> 24);
    const int b  = g_batch[n];

    const float* __restrict__ plane = feat + ((size_t)b * 256 + c) * PLANE;

    float m = -FLT_MAX;
    for (int h = h0; h < h1; ++h) {
        const float* rowp = plane + h * 50;
        for (int w = w0; w < w1; ++w) {
            m = fmaxf(m, __ldg(rowp + w));
        }
    }

    out[idx] = (w1 > w0 && h1 > h0) ? m : 0.0f;
}

extern "C" void kernel_launch(void* const* d_in, const int* in_sizes, int n_in,
                              void* d_out, int out_size)
{
    const float* feat = nullptr;
    const float* rois = nullptr;
    for (int i = 0; i < n_in; ++i) {
        long s = in_sizes[i];
        if (s == 2560000L || s == 10240000L) feat = (const float*)d_in[i];
        else if (s == 640L || s == 2560L)    rois = (const float*)d_in[i];
    }
    if (!feat) feat = (const float*)d_in[0];
    if (!rois) rois = (const float*)d_in[n_in > 1 ? 1 : 0];

    edges_kernel<<<(NROI * NBINS + 255) / 256, 256>>>(rois);   // 25 blocks
    pool_kernel<<<(OUT_ELEMS + 255) / 256, 256>>>(feat, (float*)d_out);
}